// round 8
// baseline (speedup 1.0000x reference)
#include <cuda_runtime.h>
#include <cuda_bf16.h>
#include <math.h>

#define C   64
#define HW  64
#define NSP 4096          // N = HW*HW spatial positions
#define BB  8             // batch
#define EPSBN 1e-5f

// attention tiling
#define TNQ 256           // query rows per CTA (8 warps x 32 rows)
#define TMK 64            // key/value chunk
#define PK64 68           // K smem pitch (u64): [16 slots][64 j]   (68 mod 16 == 4)
#define PV64 20           // V smem pitch (u64): [64 d][16 slots]   (20 mod 16 == 4)

// scale: (1/8) * log2(e)  -> logits in log2 domain, exp == exp2
#define QSCALE 0.18033688f

// scratch (no allocations allowed -> device globals)
// K: u64 slot s = ks*4+q holds bf16x2 of d-pairs (ks*8+q) [lo] and (ks*8+q+4) [hi]
__device__ unsigned long long g_K64[BB * 16 * NSP];
// V: u64 slot (d, chunk, t=jt*4+q) holds bf16x2 j-pairs (jt*8+q) [lo], (jt*8+q+4) [hi]
__device__ unsigned long long g_V64[BB * 64 * 64 * 16];
__device__ float g_attn[BB * C * NSP];       // attention output

// ---------------------------------------------------------------------------
// helpers
// ---------------------------------------------------------------------------
__device__ __forceinline__ unsigned packbf16(float lo, float hi) {
    unsigned r;
    asm("cvt.rn.bf16x2.f32 %0, %1, %2;" : "=r"(r) : "f"(hi), "f"(lo));
    return r;
}

__device__ __forceinline__ float ex2(float x) {
    float r;
    asm("ex2.approx.ftz.f32 %0, %1;" : "=f"(r) : "f"(x));
    return r;
}

__device__ __forceinline__ void mma_bf16(float c[4],
                                         unsigned a0, unsigned a1, unsigned a2, unsigned a3,
                                         unsigned b0, unsigned b1) {
    asm volatile(
        "mma.sync.aligned.m16n8k16.row.col.f32.bf16.bf16.f32 "
        "{%0,%1,%2,%3},{%4,%5,%6,%7},{%8,%9},{%0,%1,%2,%3};\n"
        : "+f"(c[0]), "+f"(c[1]), "+f"(c[2]), "+f"(c[3])
        : "r"(a0), "r"(a1), "r"(a2), "r"(a3), "r"(b0), "r"(b1));
}

__device__ __forceinline__ void cpa16(unsigned smem_addr, const void* gptr) {
    asm volatile("cp.async.cg.shared.global [%0], [%1], 16;"
                 :: "r"(smem_addr), "l"(gptr));
}

// ---------------------------------------------------------------------------
// conv1x1 (w1) + BN1 + ReLU -> g_V64 (bf16x2, fragment-pair packed)
// also packs K = x into g_K64 (bf16x2, fragment-pair packed)
// ---------------------------------------------------------------------------
__global__ __launch_bounds__(256) void conv1_kernel(
    const float* __restrict__ x, const float* __restrict__ w1,
    const float* __restrict__ g, const float* __restrict__ bb,
    const float* __restrict__ m, const float* __restrict__ v)
{
    __shared__ float ws[C * C];
    __shared__ float s_inv[C], s_shift[C];
    int tid = threadIdx.x;
    for (int i = tid; i < C * C; i += 256) ws[i] = w1[i];
    if (tid < C) {
        float inv = g[tid] * rsqrtf(v[tid] + EPSBN);
        s_inv[tid] = inv;
        s_shift[tid] = bb[tid] - m[tid] * inv;
    }
    __syncthreads();

    int h = tid >> 7;                 // output half (warp-uniform)
    int p = tid & 127;
    int b = blockIdx.y;
    int n = blockIdx.x * 128 + p;
    const float* xp = x + (size_t)b * C * NSP + n;
    float xv[C];
#pragma unroll
    for (int c = 0; c < C; c++) xv[c] = xp[(size_t)c * NSP];

    // ---- K packing (h==0 threads): 16 u64 slots per position ----
    if (h == 0) {
        unsigned long long* kp = g_K64 + (size_t)b * 16 * NSP + n;
#pragma unroll
        for (int s = 0; s < 16; s++) {
            int ks = s >> 2, q = s & 3;
            int dlo = ks * 8 + q, dhi = dlo + 4;
            unsigned lo = packbf16(xv[2 * dlo], xv[2 * dlo + 1]);
            unsigned hi = packbf16(xv[2 * dhi], xv[2 * dhi + 1]);
            kp[(size_t)s * NSP] = (unsigned long long)lo | ((unsigned long long)hi << 32);
        }
    }

    // ---- conv + BN + ReLU into registers ----
    float vout[32];
    int o0 = h * 32;
#pragma unroll 4
    for (int oo = 0; oo < 32; oo++) {
        int o = o0 + oo;
        const float4* wr = (const float4*)(ws + o * C);
        float a0 = 0.f, a1 = 0.f, a2 = 0.f, a3 = 0.f;
#pragma unroll
        for (int k = 0; k < 16; k++) {
            float4 f = wr[k];
            a0 += f.x * xv[4 * k + 0];
            a1 += f.y * xv[4 * k + 1];
            a2 += f.z * xv[4 * k + 2];
            a3 += f.w * xv[4 * k + 3];
        }
        float acc = (a0 + a1) + (a2 + a3);
        vout[oo] = fmaxf(acc * s_inv[o] + s_shift[o], 0.f);
    }

    // ---- V packing: n-pairs via shuffle, write u32 half of u64 slot ----
    {
        bool evenl = !(n & 1);
        int np = n >> 1;
        int ch = n >> 6;
        int jp = np & 31;
        int qq = jp & 7, jt = jp >> 3;
        int t = (qq < 4) ? (jt * 4 + qq) : (jt * 4 + qq - 4);
        int half = (qq < 4) ? 0 : 1;
        unsigned* vp32 = (unsigned*)g_V64;
#pragma unroll
        for (int oo = 0; oo < 32; oo++) {
            float other = __shfl_down_sync(0xffffffffu, vout[oo], 1);
            if (evenl) {
                int d = o0 + oo;
                size_t idx = ((((size_t)b * 64 + d) * 64 + ch) * 16 + t) * 2 + half;
                vp32[idx] = packbf16(vout[oo], other);
            }
        }
    }
}

// ---------------------------------------------------------------------------
// flash attention, bf16 m16n8k16, no-max softmax, Q in regs,
// K/V double-buffered cp.async; fragment pairs as single LDS.64.
// CTA = (batch, 256 rows); 8 warps x 32 rows; grid 128 CTAs = 1 wave.
// ---------------------------------------------------------------------------
__global__ __launch_bounds__(256) void attn_mma_kernel(const float* __restrict__ x)
{
    __shared__ __align__(16) unsigned long long Ks64[2][16 * PK64];
    __shared__ __align__(16) unsigned long long Vs64[2][64 * PV64];

    const int tid  = threadIdx.x;
    const int lane = tid & 31;
    const int wid  = tid >> 5;
    const int g    = lane >> 2;       // 0..7
    const int q    = lane & 3;        // 0..3
    const int i0   = wid * 32;

    const int b  = blockIdx.y;
    const int n0 = blockIdx.x * TNQ;
    const float* xb = x + (size_t)b * C * NSP;
    const unsigned long long* kb64 = g_K64 + (size_t)b * 16 * NSP;
    const unsigned long long* vb64 = g_V64 + (size_t)b * 64 * 64 * 16;

    unsigned ksa[2], vsa[2];
    ksa[0] = (unsigned)__cvta_generic_to_shared(&Ks64[0][0]);
    ksa[1] = (unsigned)__cvta_generic_to_shared(&Ks64[1][0]);
    vsa[0] = (unsigned)__cvta_generic_to_shared(&Vs64[0][0]);
    vsa[1] = (unsigned)__cvta_generic_to_shared(&Vs64[1][0]);
    const int i2  = tid * 2;
    const int i2b = i2 + 512;

    // ---- Q A-fragments straight into registers (scale folded) ----
    unsigned QA[4][2][4];
#pragma unroll
    for (int ks = 0; ks < 4; ks++) {
#pragma unroll
        for (int rb = 0; rb < 2; rb++) {
            int re = n0 + i0 + rb * 16 + g;
            int d0 = 16 * ks + 2 * q;
            QA[ks][rb][0] = packbf16(xb[(size_t)d0 * NSP + re] * QSCALE,
                                     xb[(size_t)(d0 + 1) * NSP + re] * QSCALE);
            QA[ks][rb][1] = packbf16(xb[(size_t)d0 * NSP + re + 8] * QSCALE,
                                     xb[(size_t)(d0 + 1) * NSP + re + 8] * QSCALE);
            QA[ks][rb][2] = packbf16(xb[(size_t)(d0 + 8) * NSP + re] * QSCALE,
                                     xb[(size_t)(d0 + 9) * NSP + re] * QSCALE);
            QA[ks][rb][3] = packbf16(xb[(size_t)(d0 + 8) * NSP + re + 8] * QSCALE,
                                     xb[(size_t)(d0 + 9) * NSP + re + 8] * QSCALE);
        }
    }

    float SC[2][8][4];
    float OC[2][8][4];
    unsigned PH[2][8][2];
#pragma unroll
    for (int rb = 0; rb < 2; rb++)
#pragma unroll
        for (int t = 0; t < 8; t++)
            OC[rb][t][0] = OC[rb][t][1] = OC[rb][t][2] = OC[rb][t][3] = 0.f;
    float rl[2][2] = {{0.f, 0.f}, {0.f, 0.f}};

    // issue K/V chunk m0 into buffer buf (each thread: 2 K + 2 V 16B copies)
    #define ISSUE_CHUNK(m0, buf) do {                                                   \
        int _ch = (m0) >> 6;                                                            \
        cpa16(ksa[buf] + ((i2  >> 6) * PK64 + (i2  & 63)) * 8,                          \
              kb64 + (size_t)(i2  >> 6) * NSP + (m0) + (i2  & 63));                     \
        cpa16(ksa[buf] + ((i2b >> 6) * PK64 + (i2b & 63)) * 8,                          \
              kb64 + (size_t)(i2b >> 6) * NSP + (m0) + (i2b & 63));                     \
        cpa16(vsa[buf] + ((i2  >> 4) * PV64 + (i2  & 15)) * 8,                          \
              vb64 + (size_t)((i2  >> 4) * 64 + _ch) * 16 + (i2  & 15));                \
        cpa16(vsa[buf] + ((i2b >> 4) * PV64 + (i2b & 15)) * 8,                          \
              vb64 + (size_t)((i2b >> 4) * 64 + _ch) * 16 + (i2b & 15));                \
        asm volatile("cp.async.commit_group;");                                         \
    } while (0)

    ISSUE_CHUNK(0, 0);

    for (int mm = 0; mm < NSP / TMK; mm++) {
        int cur = mm & 1;
        if (mm + 1 < NSP / TMK) {
            ISSUE_CHUNK((mm + 1) * TMK, 1 - cur);
            asm volatile("cp.async.wait_group 1;");
        } else {
            asm volatile("cp.async.wait_group 0;");
        }
        __syncthreads();

        const uint2* Kc = (const uint2*)&Ks64[cur][0];
        const uint2* Vc = (const uint2*)&Vs64[cur][0];

        // ---- S = Q K^T ----
#pragma unroll
        for (int rb = 0; rb < 2; rb++)
#pragma unroll
            for (int t = 0; t < 8; t++)
                SC[rb][t][0] = SC[rb][t][1] = SC[rb][t][2] = SC[rb][t][3] = 0.f;
#pragma unroll
        for (int ks = 0; ks < 4; ks++) {
            int srow = (ks * 4 + q) * PK64;
#pragma unroll
            for (int nt = 0; nt < 8; nt++) {
                uint2 kf = Kc[srow + nt * 8 + g];
                mma_bf16(SC[0][nt], QA[ks][0][0], QA[ks][0][1], QA[ks][0][2], QA[ks][0][3], kf.x, kf.y);
                mma_bf16(SC[1][nt], QA[ks][1][0], QA[ks][1][1], QA[ks][1][2], QA[ks][1][3], kf.x, kf.y);
            }
        }

        // ---- P = exp2(S); row sums; pack to A-fragments ----
#pragma unroll
        for (int rb = 0; rb < 2; rb++) {
#pragma unroll
            for (int nt = 0; nt < 8; nt++) {
                float e0 = ex2(SC[rb][nt][0]);
                float e1 = ex2(SC[rb][nt][1]);
                float e2 = ex2(SC[rb][nt][2]);
                float e3 = ex2(SC[rb][nt][3]);
                rl[rb][0] += e0 + e1;
                rl[rb][1] += e2 + e3;
                PH[rb][nt][0] = packbf16(e0, e1);
                PH[rb][nt][1] = packbf16(e2, e3);
            }
        }

        // ---- O += P V ----
#pragma unroll
        for (int jt = 0; jt < 4; jt++) {
            unsigned aA0 = PH[0][2 * jt][0],     aA1 = PH[0][2 * jt][1];
            unsigned aA2 = PH[0][2 * jt + 1][0], aA3 = PH[0][2 * jt + 1][1];
            unsigned aB0 = PH[1][2 * jt][0],     aB1 = PH[1][2 * jt][1];
            unsigned aB2 = PH[1][2 * jt + 1][0], aB3 = PH[1][2 * jt + 1][1];
#pragma unroll
            for (int nt2 = 0; nt2 < 8; nt2++) {
                uint2 vf = Vc[(nt2 * 8 + g) * PV64 + jt * 4 + q];
                mma_bf16(OC[0][nt2], aA0, aA1, aA2, aA3, vf.x, vf.y);
                mma_bf16(OC[1][nt2], aB0, aB1, aB2, aB3, vf.x, vf.y);
            }
        }
        __syncthreads();
    }

    // ---- final row-sum reduction ----
#pragma unroll
    for (int rb = 0; rb < 2; rb++) {
        rl[rb][0] += __shfl_xor_sync(0xffffffffu, rl[rb][0], 1);
        rl[rb][0] += __shfl_xor_sync(0xffffffffu, rl[rb][0], 2);
        rl[rb][1] += __shfl_xor_sync(0xffffffffu, rl[rb][1], 1);
        rl[rb][1] += __shfl_xor_sync(0xffffffffu, rl[rb][1], 2);
    }

    // ---- normalize + write ----
#pragma unroll
    for (int rb = 0; rb < 2; rb++) {
        float inv0 = 1.f / rl[rb][0], inv1 = 1.f / rl[rb][1];
        float* ob = g_attn + (size_t)b * C * NSP + n0 + i0 + rb * 16 + g;
#pragma unroll
        for (int nt2 = 0; nt2 < 8; nt2++) {
            int d0 = nt2 * 8 + 2 * q;
            ob[(size_t)d0 * NSP]           = OC[rb][nt2][0] * inv0;
            ob[(size_t)(d0 + 1) * NSP]     = OC[rb][nt2][1] * inv0;
            ob[(size_t)d0 * NSP + 8]       = OC[rb][nt2][2] * inv1;
            ob[(size_t)(d0 + 1) * NSP + 8] = OC[rb][nt2][3] * inv1;
        }
    }
    #undef ISSUE_CHUNK
}

// ---------------------------------------------------------------------------
// fused tail: depthwise 3x3 + BN2 + ReLU -> smem -> conv1x1 (w3) + BN3 + resid
// CTA = (image row y, batch b); 256 threads.
//   phase 1: thread (c, xg) computes dw for channel c, 16 x-positions -> Us
//   phase 2: thread (x, h) computes 16 output channels at position x
// ---------------------------------------------------------------------------
#define USP 65
__global__ __launch_bounds__(256) void tail_kernel(
    const float* __restrict__ w2,
    const float* __restrict__ g2, const float* __restrict__ b2,
    const float* __restrict__ m2, const float* __restrict__ v2,
    const float* __restrict__ w3,
    const float* __restrict__ g3, const float* __restrict__ b3,
    const float* __restrict__ m3, const float* __restrict__ v3,
    const float* __restrict__ x, float* __restrict__ out)
{
    __shared__ float ws[C * C];
    __shared__ float Us[C * USP];
    __shared__ float s_inv[C], s_shift[C];

    int tid = threadIdx.x;
    int y = blockIdx.x;
    int b = blockIdx.y;

    for (int i = tid; i < C * C; i += 256) ws[i] = w3[i];
    if (tid < C) {
        float inv = g3[tid] * rsqrtf(v3[tid] + EPSBN);
        s_inv[tid] = inv;
        s_shift[tid] = b3[tid] - m3[tid] * inv;
    }

    // ---- phase 1: depthwise for row y ----
    {
        int c = tid & 63, xg = tid >> 6, x0 = xg * 16;
        const float* ip = g_attn + ((size_t)(b * 64 + c) << 12);
        float wr[9];
#pragma unroll
        for (int k = 0; k < 9; k++) wr[k] = w2[c * 9 + k];

        float acc[16];
#pragma unroll
        for (int k = 0; k < 16; k++) acc[k] = 0.f;

#pragma unroll
        for (int dy = -1; dy <= 1; dy++) {
            int yy = y + dy;
            if (yy < 0 || yy >= HW) continue;
            const float* rp = ip + yy * HW + x0;
            float fin[18];
            fin[0] = (x0 > 0) ? rp[-1] : 0.f;
            float4 m0 = *(const float4*)(rp);
            float4 m1 = *(const float4*)(rp + 4);
            float4 m2v = *(const float4*)(rp + 8);
            float4 m3v = *(const float4*)(rp + 12);
            fin[1] = m0.x;  fin[2] = m0.y;  fin[3] = m0.z;  fin[4] = m0.w;
            fin[5] = m1.x;  fin[6] = m1.y;  fin[7] = m1.z;  fin[8] = m1.w;
            fin[9] = m2v.x; fin[10] = m2v.y; fin[11] = m2v.z; fin[12] = m2v.w;
            fin[13] = m3v.x; fin[14] = m3v.y; fin[15] = m3v.z; fin[16] = m3v.w;
            fin[17] = (x0 + 16 < HW) ? rp[16] : 0.f;
            float c0 = wr[(dy + 1) * 3 + 0];
            float c1 = wr[(dy + 1) * 3 + 1];
            float c2 = wr[(dy + 1) * 3 + 2];
#pragma unroll
            for (int k = 0; k < 16; k++)
                acc[k] += c0 * fin[k] + c1 * fin[k + 1] + c2 * fin[k + 2];
        }
        float inv = g2[c] * rsqrtf(v2[c] + EPSBN);
        float sh = b2[c] - m2[c] * inv;
#pragma unroll
        for (int k = 0; k < 16; k++)
            Us[c * USP + x0 + k] = fmaxf(acc[k] * inv + sh, 0.f);
    }
    __syncthreads();

    // ---- phase 2: conv1x1 + BN3 + residual ----
    {
        int xx = tid & 63, h = tid >> 6;
        int n = y * HW + xx;
        float uv[C];
#pragma unroll
        for (int c = 0; c < C; c++) uv[c] = Us[c * USP + xx];

        const float* xp = x + (size_t)b * C * NSP + n;
        float* op = out + (size_t)b * C * NSP + n;
        int o0 = h * 16;
#pragma unroll 4
        for (int o = o0; o < o0 + 16; o++) {
            const float4* wrr = (const float4*)(ws + o * C);
            float a0 = 0.f, a1 = 0.f, a2 = 0.f, a3 = 0.f;
#pragma unroll
            for (int k = 0; k < 16; k++) {
                float4 f = wrr[k];
                a0 += f.x * uv[4 * k + 0];
                a1 += f.y * uv[4 * k + 1];
                a2 += f.z * uv[4 * k + 2];
                a3 += f.w * uv[4 * k + 3];
            }
            float acc = (a0 + a1) + (a2 + a3);
            float r = acc * s_inv[o] + s_shift[o] + xp[(size_t)o * NSP];
            op[(size_t)o * NSP] = r;
        }
    }
}

// ---------------------------------------------------------------------------
extern "C" void kernel_launch(void* const* d_in, const int* in_sizes, int n_in,
                              void* d_out, int out_size)
{
    const float* x    = (const float*)d_in[0];
    const float* w1   = (const float*)d_in[1];
    const float* bn1g = (const float*)d_in[2];
    const float* bn1b = (const float*)d_in[3];
    const float* bn1m = (const float*)d_in[4];
    const float* bn1v = (const float*)d_in[5];
    const float* w2   = (const float*)d_in[6];
    const float* bn2g = (const float*)d_in[7];
    const float* bn2b = (const float*)d_in[8];
    const float* bn2m = (const float*)d_in[9];
    const float* bn2v = (const float*)d_in[10];
    const float* w3   = (const float*)d_in[11];
    const float* bn3g = (const float*)d_in[12];
    const float* bn3b = (const float*)d_in[13];
    const float* bn3m = (const float*)d_in[14];
    const float* bn3v = (const float*)d_in[15];
    float* out = (float*)d_out;

    conv1_kernel<<<dim3(NSP / 128, BB), 256>>>(x, w1, bn1g, bn1b, bn1m, bn1v);
    attn_mma_kernel<<<dim3(NSP / TNQ, BB), 256>>>(x);
    tail_kernel<<<dim3(HW, BB), 256>>>(w2, bn2g, bn2b, bn2m, bn2v,
                                       w3, bn3g, bn3b, bn3m, bn3v, x, out);
}